// round 1
// baseline (speedup 1.0000x reference)
#include <cuda_runtime.h>

// Problem constants (fixed by the dataset)
#define BB 4
#define CC 256
#define HW 4096

// ---------------- scratch (no allocations allowed -> device globals) -------
__device__ float g_Q [(size_t)BB * HW * CC];        // [b][n][c]   67 MB
__device__ float g_K [(size_t)BB * CC * HW];        // [b][c][m]   67 MB
__device__ float g_VV[(size_t)BB * HW * 2 * CC];    // [b][m][c|c+256] 134 MB
__device__ float g_S [(size_t)BB * HW * HW];        // [b][n][m]   268 MB
__device__ float g_ME[(size_t)BB * HW * 2 * CC];    // [b][n][mean|E2] 134 MB
__device__ float g_cmean[BB * CC];
__device__ float g_cinv [BB * CC];

// ---------------------------------------------------------------------------
// Generic 128x128x8 fp32 SGEMM, 256 threads, 8x8 micro-tile per thread.
// All problem dims here are multiples of the tile sizes, so no bounds checks.
// MODE 0: C[row*N+col] = v                     (plain)
// MODE 1: C[col*M+row] = v + bias[row]         (Q: transposed store)
// MODE 2: C[row*N+col] = v + bias[row]         (K: natural + bias)
// MODE 3: C[col*2M+row] = t; C[col*2M+M+row]=t*t  (V and V^2 interleaved)
// ---------------------------------------------------------------------------
template <int MODE>
__global__ __launch_bounds__(256) void sgemm_k(
    const float* __restrict__ A, const float* __restrict__ B,
    const float* __restrict__ bias, float* __restrict__ Cout,
    int M, int N, int K,
    long long strA, long long strB, long long strC)
{
    A    += (long long)blockIdx.z * strA;
    B    += (long long)blockIdx.z * strB;
    Cout += (long long)blockIdx.z * strC;

    __shared__ float sA[8][128];
    __shared__ float sB[8][128];

    const int tid = threadIdx.x;
    const int bm  = blockIdx.y * 128;
    const int bn  = blockIdx.x * 128;
    const int tx  = tid & 15;
    const int ty  = tid >> 4;

    const int arow = tid >> 1;        // 0..127
    const int acol = (tid & 1) * 4;   // 0 or 4
    const int brow = tid >> 5;        // 0..7
    const int bcol = (tid & 31) * 4;  // 0..124

    float acc[8][8];
#pragma unroll
    for (int i = 0; i < 8; i++)
#pragma unroll
        for (int j = 0; j < 8; j++) acc[i][j] = 0.f;

    for (int k0 = 0; k0 < K; k0 += 8) {
        float4 av = *reinterpret_cast<const float4*>(
            A + (long long)(bm + arow) * K + k0 + acol);
        float4 bv = *reinterpret_cast<const float4*>(
            B + (long long)(k0 + brow) * N + bn + bcol);
        __syncthreads();  // previous iteration's reads done
        sA[acol + 0][arow] = av.x;
        sA[acol + 1][arow] = av.y;
        sA[acol + 2][arow] = av.z;
        sA[acol + 3][arow] = av.w;
        *reinterpret_cast<float4*>(&sB[brow][bcol]) = bv;
        __syncthreads();
#pragma unroll
        for (int kk = 0; kk < 8; kk++) {
            float a[8], bb[8];
#pragma unroll
            for (int i = 0; i < 8; i++) a[i]  = sA[kk][ty * 8 + i];
#pragma unroll
            for (int j = 0; j < 8; j++) bb[j] = sB[kk][tx * 8 + j];
#pragma unroll
            for (int i = 0; i < 8; i++)
#pragma unroll
                for (int j = 0; j < 8; j++)
                    acc[i][j] = fmaf(a[i], bb[j], acc[i][j]);
        }
    }

#pragma unroll
    for (int i = 0; i < 8; i++) {
        const int row = bm + ty * 8 + i;
#pragma unroll
        for (int j = 0; j < 8; j++) {
            const int col = bn + tx * 8 + j;
            float v = acc[i][j];
            if (MODE == 0) {
                Cout[(long long)row * N + col] = v;
            } else if (MODE == 1) {
                Cout[(long long)col * M + row] = v + bias[row];
            } else if (MODE == 2) {
                Cout[(long long)row * N + col] = v + bias[row];
            } else {
                float t = v + bias[row];
                Cout[(long long)col * (2 * M) + row]     = t;
                Cout[(long long)col * (2 * M) + M + row] = t * t;
            }
        }
    }
}

// ---------------------------------------------------------------------------
// Row softmax over 4096 columns, one block (256 thr) per row, in-place.
// ---------------------------------------------------------------------------
__global__ __launch_bounds__(256) void softmax_k()
{
    __shared__ float red[8];
    const size_t row = blockIdx.x;
    float4* p = reinterpret_cast<float4*>(g_S + row * (size_t)HW);
    const int tid = threadIdx.x;

    float4 v[4];
    float mx = -3.4e38f;
#pragma unroll
    for (int i = 0; i < 4; i++) {
        v[i] = p[tid + i * 256];
        mx = fmaxf(mx, fmaxf(fmaxf(v[i].x, v[i].y), fmaxf(v[i].z, v[i].w)));
    }
#pragma unroll
    for (int o = 16; o > 0; o >>= 1)
        mx = fmaxf(mx, __shfl_xor_sync(0xffffffffu, mx, o));
    if ((tid & 31) == 0) red[tid >> 5] = mx;
    __syncthreads();
    mx = red[0];
#pragma unroll
    for (int i = 1; i < 8; i++) mx = fmaxf(mx, red[i]);

    float s = 0.f;
#pragma unroll
    for (int i = 0; i < 4; i++) {
        v[i].x = __expf(v[i].x - mx);
        v[i].y = __expf(v[i].y - mx);
        v[i].z = __expf(v[i].z - mx);
        v[i].w = __expf(v[i].w - mx);
        s += v[i].x + v[i].y + v[i].z + v[i].w;
    }
#pragma unroll
    for (int o = 16; o > 0; o >>= 1)
        s += __shfl_xor_sync(0xffffffffu, s, o);
    __syncthreads();  // all done reading red (max phase)
    if ((tid & 31) == 0) red[tid >> 5] = s;
    __syncthreads();
    s = red[0];
#pragma unroll
    for (int i = 1; i < 8; i++) s += red[i];

    const float inv = 1.0f / s;
#pragma unroll
    for (int i = 0; i < 4; i++) {
        v[i].x *= inv; v[i].y *= inv; v[i].z *= inv; v[i].w *= inv;
        p[tid + i * 256] = v[i];
    }
}

// ---------------------------------------------------------------------------
// Per-(b,c) mean / inv-std of content over HW (unbiased var, ddof=1).
// One block per (b,c).
// ---------------------------------------------------------------------------
__global__ __launch_bounds__(256) void stats_k(const float* __restrict__ content)
{
    __shared__ float r1[8];
    __shared__ float r2[8];
    const int bc = blockIdx.x;  // 0..BB*CC-1
    const float4* p = reinterpret_cast<const float4*>(content + (size_t)bc * HW);
    const int tid = threadIdx.x;

    float s = 0.f, s2 = 0.f;
#pragma unroll
    for (int i = 0; i < 4; i++) {
        float4 v = p[tid + i * 256];
        s  += v.x + v.y + v.z + v.w;
        s2 += v.x * v.x + v.y * v.y + v.z * v.z + v.w * v.w;
    }
#pragma unroll
    for (int o = 16; o > 0; o >>= 1) {
        s  += __shfl_xor_sync(0xffffffffu, s, o);
        s2 += __shfl_xor_sync(0xffffffffu, s2, o);
    }
    if ((tid & 31) == 0) { r1[tid >> 5] = s; r2[tid >> 5] = s2; }
    __syncthreads();
    if (tid == 0) {
        float ts = 0.f, ts2 = 0.f;
#pragma unroll
        for (int i = 0; i < 8; i++) { ts += r1[i]; ts2 += r2[i]; }
        float mean = ts * (1.0f / HW);
        float var  = (ts2 - (float)HW * mean * mean) * (1.0f / (HW - 1));
        g_cmean[bc] = mean;
        g_cinv[bc]  = rsqrtf(var + 1e-5f);
    }
}

// ---------------------------------------------------------------------------
// out[b,c,n] = std[b,n,c] * (content[b,c,n]-m[b,c])*inv[b,c] + mean[b,n,c]
// ---------------------------------------------------------------------------
__global__ __launch_bounds__(256) void final_k(const float* __restrict__ content,
                                               float* __restrict__ out)
{
    const size_t idx = (size_t)blockIdx.x * 256 + threadIdx.x;  // b,c,n linear
    const int b = (int)(idx >> 20);          // CC*HW = 2^20
    const int c = (int)((idx >> 12) & 255);  // HW = 2^12
    const int n = (int)(idx & 4095);
    const float* me = g_ME + ((size_t)(b * HW + n)) * (2 * CC);
    const float m  = me[c];
    const float e2 = me[CC + c];
    const float sd = sqrtf(fmaxf(e2 - m * m, 0.f));
    const int bc = b * CC + c;
    out[idx] = sd * (content[idx] - g_cmean[bc]) * g_cinv[bc] + m;
}

// ---------------------------------------------------------------------------
extern "C" void kernel_launch(void* const* d_in, const int* in_sizes, int n_in,
                              void* d_out, int out_size)
{
    const float* content = (const float*)d_in[0];
    const float* style   = (const float*)d_in[1];
    const float* ckey    = (const float*)d_in[2];
    const float* skey    = (const float*)d_in[3];
    const float* Wf = (const float*)d_in[4];
    const float* bf = (const float*)d_in[5];
    const float* Wg = (const float*)d_in[6];
    const float* bg = (const float*)d_in[7];
    const float* Wh = (const float*)d_in[8];
    const float* bh = (const float*)d_in[9];
    float* out = (float*)d_out;

    float *Q, *Kp, *VV, *S, *ME;
    cudaGetSymbolAddress((void**)&Q,  g_Q);
    cudaGetSymbolAddress((void**)&Kp, g_K);
    cudaGetSymbolAddress((void**)&VV, g_VV);
    cudaGetSymbolAddress((void**)&S,  g_S);
    cudaGetSymbolAddress((void**)&ME, g_ME);

    const dim3 blk(256);
    const long long sCHW = (long long)CC * HW;

    // Projections: R[o,p] = W[o,c] X[b,c,p] + bias[o]   (M=256,N=4096,K=256)
    sgemm_k<1><<<dim3(32, 2, BB), blk>>>(Wf, ckey, bf, Q,  CC, HW, CC,
                                         0, sCHW, (long long)HW * CC);
    sgemm_k<2><<<dim3(32, 2, BB), blk>>>(Wg, skey, bg, Kp, CC, HW, CC,
                                         0, sCHW, sCHW);
    sgemm_k<3><<<dim3(32, 2, BB), blk>>>(Wh, style, bh, VV, CC, HW, CC,
                                         0, sCHW, (long long)HW * 2 * CC);

    // Logits: S[b,n,m] = Q[b,n,:] . K[b,:,m]   (M=4096,N=4096,K=256)
    sgemm_k<0><<<dim3(32, 32, BB), blk>>>(Q, Kp, nullptr, S, HW, HW, CC,
                                          (long long)HW * CC, sCHW,
                                          (long long)HW * HW);

    // Row softmax (in place)
    softmax_k<<<BB * HW, blk>>>();

    // [mean|E2][b,n,c512] = S[b,n,:] @ VV[b,:,c512]   (M=4096,N=512,K=4096)
    sgemm_k<0><<<dim3(4, 32, BB), blk>>>(S, VV, nullptr, ME, HW, 2 * CC, HW,
                                         (long long)HW * HW,
                                         (long long)HW * 2 * CC,
                                         (long long)HW * 2 * CC);

    // Content channel stats + final fused modulation
    stats_k<<<BB * CC, blk>>>(content);
    final_k<<<(BB * CC * HW) / 256, blk>>>(content, out);
}

// round 3
// speedup vs baseline: 1.8544x; 1.8544x over previous
#include <cuda_runtime.h>
#include <cuda_fp16.h>
#include <cstdint>

// Problem constants (fixed by the dataset)
#define BB 4
#define CC 256
#define HW 4096

// ---------------- scratch (no allocations allowed -> device globals) -------
__device__ float g_Q  [(size_t)BB * HW * CC];         // [b][n][c]
__device__ float g_Kt [(size_t)BB * HW * CC];         // [b][m][c]
__device__ float g_VVt[(size_t)BB * 2 * CC * HW];     // [b][c2][m]
__device__ float g_S  [(size_t)BB * HW * HW];         // [b][n][m]
__device__ float g_ME [(size_t)BB * HW * 2 * CC];     // [b][n][c2] (mean | E2)
__device__ float g_cmean[BB * CC];
__device__ float g_cinv [BB * CC];

// =========================== MMA helpers (baseline PTX, sm_80+) ============
#define LDSM4(r, addr) \
    asm volatile("ldmatrix.sync.aligned.m8n8.x4.shared.b16 {%0,%1,%2,%3}, [%4];" \
        : "=r"((r)[0]), "=r"((r)[1]), "=r"((r)[2]), "=r"((r)[3]) : "r"(addr))

#define MMA16816(d, a, b0, b1) \
    asm volatile("mma.sync.aligned.m16n8k16.row.col.f32.f16.f16.f32 " \
        "{%0,%1,%2,%3}, {%4,%5,%6,%7}, {%8,%9}, {%0,%1,%2,%3};" \
        : "+f"((d)[0]), "+f"((d)[1]), "+f"((d)[2]), "+f"((d)[3]) \
        : "r"((a)[0]), "r"((a)[1]), "r"((a)[2]), "r"((a)[3]), "r"(b0), "r"(b1))

// ===========================================================================
// HMMA fp16 3-pass split GEMM:  C[M x N] = A[M x K] @ B[N x K]^T  (fp32 in/out)
// CTA 128x128, 8 warps (4M x 2N), warp tile 32x64, k-step 32.
// SMEM pitch 40 halves (80B) -> conflict-free ldmatrix.
// grid = (N/128, M/128, batch)
// ===========================================================================
#define PITCH 40

__global__ __launch_bounds__(256) void hmma_gemm(
    const float* __restrict__ A, const float* __restrict__ B,
    float* __restrict__ C, int K, int ldc,
    long long strA, long long strB, long long strC)
{
    __shared__ __half sAh[128 * PITCH], sAl[128 * PITCH];
    __shared__ __half sBh[128 * PITCH], sBl[128 * PITCH];

    const int tid  = threadIdx.x;
    const int lane = tid & 31;
    const int wid  = tid >> 5;
    const int wm   = wid & 3;   // warp row (0..3) -> 32 M each
    const int wn   = wid >> 2;  // warp col (0..1) -> 64 N each

    A += blockIdx.z * strA + (long long)(blockIdx.y * 128) * K;
    B += blockIdx.z * strB + (long long)(blockIdx.x * 128) * K;
    C += blockIdx.z * strC + (long long)(blockIdx.y * 128) * ldc + blockIdx.x * 128;

    float acc[2][8][4];
#pragma unroll
    for (int i = 0; i < 2; i++)
#pragma unroll
        for (int j = 0; j < 8; j++)
#pragma unroll
            for (int t = 0; t < 4; t++) acc[i][j][t] = 0.f;

    // per-thread global-load pattern: fixed 16B column, 4 rows (stride 32)
    const int grow = tid >> 3;        // 0..31
    const int gcol = (tid & 7) * 4;   // float index 0..28

    float4 ra[4], rb[4];
#pragma unroll
    for (int i = 0; i < 4; i++) {
        ra[i] = *reinterpret_cast<const float4*>(A + (long long)(grow + i * 32) * K + gcol);
        rb[i] = *reinterpret_cast<const float4*>(B + (long long)(grow + i * 32) * K + gcol);
    }

    // ldmatrix per-lane addressing
    const int grp  = lane >> 3;   // 0..3
    const int lrow = lane & 7;
    const uint32_t uAh = (uint32_t)__cvta_generic_to_shared(sAh);
    const uint32_t uAl = (uint32_t)__cvta_generic_to_shared(sAl);
    const uint32_t uBh = (uint32_t)__cvta_generic_to_shared(sBh);
    const uint32_t uBl = (uint32_t)__cvta_generic_to_shared(sBl);

    for (int k0 = 0; k0 < K; k0 += 32) {
        __syncthreads();
        // ---- convert + store staged tiles ----
#pragma unroll
        for (int i = 0; i < 4; i++) {
            const int row = grow + i * 32;
            float4 v = ra[i];
            __half h0 = __float2half_rn(v.x), h1 = __float2half_rn(v.y);
            __half h2 = __float2half_rn(v.z), h3 = __float2half_rn(v.w);
            __half l0 = __float2half_rn(v.x - __half2float(h0));
            __half l1 = __float2half_rn(v.y - __half2float(h1));
            __half l2 = __float2half_rn(v.z - __half2float(h2));
            __half l3 = __float2half_rn(v.w - __half2float(h3));
            __half2 ph0 = __halves2half2(h0, h1), ph1 = __halves2half2(h2, h3);
            __half2 pl0 = __halves2half2(l0, l1), pl1 = __halves2half2(l2, l3);
            *reinterpret_cast<uint2*>(sAh + row * PITCH + gcol) =
                make_uint2(*(uint32_t*)&ph0, *(uint32_t*)&ph1);
            *reinterpret_cast<uint2*>(sAl + row * PITCH + gcol) =
                make_uint2(*(uint32_t*)&pl0, *(uint32_t*)&pl1);

            v = rb[i];
            h0 = __float2half_rn(v.x); h1 = __float2half_rn(v.y);
            h2 = __float2half_rn(v.z); h3 = __float2half_rn(v.w);
            l0 = __float2half_rn(v.x - __half2float(h0));
            l1 = __float2half_rn(v.y - __half2float(h1));
            l2 = __float2half_rn(v.z - __half2float(h2));
            l3 = __float2half_rn(v.w - __half2float(h3));
            ph0 = __halves2half2(h0, h1); ph1 = __halves2half2(h2, h3);
            pl0 = __halves2half2(l0, l1); pl1 = __halves2half2(l2, l3);
            *reinterpret_cast<uint2*>(sBh + row * PITCH + gcol) =
                make_uint2(*(uint32_t*)&ph0, *(uint32_t*)&ph1);
            *reinterpret_cast<uint2*>(sBl + row * PITCH + gcol) =
                make_uint2(*(uint32_t*)&pl0, *(uint32_t*)&pl1);
        }
        __syncthreads();

        // ---- prefetch next k-step while tensor pipe works ----
        if (k0 + 32 < K) {
#pragma unroll
            for (int i = 0; i < 4; i++) {
                ra[i] = *reinterpret_cast<const float4*>(
                    A + (long long)(grow + i * 32) * K + k0 + 32 + gcol);
                rb[i] = *reinterpret_cast<const float4*>(
                    B + (long long)(grow + i * 32) * K + k0 + 32 + gcol);
            }
        }

        // ---- compute: 2 k16 sub-steps ----
#pragma unroll
        for (int ks = 0; ks < 2; ks++) {
            const int kchunk = ks * 2 + (grp >> 1);
            uint32_t aH[2][4], aL[2][4];
#pragma unroll
            for (int mt = 0; mt < 2; mt++) {
                const int row = wm * 32 + mt * 16 + lrow + ((grp & 1) << 3);
                const uint32_t off = row * (PITCH * 2) + kchunk * 16;
                LDSM4(aH[mt], uAh + off);
                LDSM4(aL[mt], uAl + off);
            }
#pragma unroll
            for (int nt4 = 0; nt4 < 4; nt4++) {
                const int brow = wn * 64 + nt4 * 16 + lrow + ((grp & 1) << 3);
                const uint32_t boff = brow * (PITCH * 2) + kchunk * 16;
                uint32_t bh[4], bl[4];
                LDSM4(bh, uBh + boff);
                LDSM4(bl, uBl + boff);
#pragma unroll
                for (int mt = 0; mt < 2; mt++) {
                    MMA16816(acc[mt][nt4 * 2],     aH[mt], bh[0], bh[2]);
                    MMA16816(acc[mt][nt4 * 2],     aL[mt], bh[0], bh[2]);
                    MMA16816(acc[mt][nt4 * 2],     aH[mt], bl[0], bl[2]);
                    MMA16816(acc[mt][nt4 * 2 + 1], aH[mt], bh[1], bh[3]);
                    MMA16816(acc[mt][nt4 * 2 + 1], aL[mt], bh[1], bh[3]);
                    MMA16816(acc[mt][nt4 * 2 + 1], aH[mt], bl[1], bl[3]);
                }
            }
        }
    }

    // ---- epilogue: fragment store ----
#pragma unroll
    for (int mt = 0; mt < 2; mt++) {
        const int lr = wm * 32 + mt * 16 + (lane >> 2);
#pragma unroll
        for (int nt = 0; nt < 8; nt++) {
            const int col = wn * 64 + nt * 8 + (lane & 3) * 2;
            *reinterpret_cast<float2*>(C + (long long)lr * ldc + col) =
                make_float2(acc[mt][nt][0], acc[mt][nt][1]);
            *reinterpret_cast<float2*>(C + (long long)(lr + 8) * ldc + col) =
                make_float2(acc[mt][nt][2], acc[mt][nt][3]);
        }
    }
}

// ===========================================================================
// SIMT projections: R[o,p] = W[o,c] X[b,c,p] + bias[o]   (M=256,N=4096,K=256)
// MODE 1: C[col*M+row] = v+bias  ([pixel][chan] -> Q, Kt)
// MODE 4: C[row*N+col] = t ; C[(row+256)*N+col] = t*t    (VVt)
// ===========================================================================
template <int MODE>
__global__ __launch_bounds__(256) void sgemm_k(
    const float* __restrict__ A, const float* __restrict__ B,
    const float* __restrict__ bias, float* __restrict__ Cout,
    int M, int N, int K, long long strB, long long strC)
{
    B    += (long long)blockIdx.z * strB;
    Cout += (long long)blockIdx.z * strC;

    __shared__ float sA[8][128];
    __shared__ float sB[8][128];

    const int tid = threadIdx.x;
    const int bm  = blockIdx.y * 128;
    const int bn  = blockIdx.x * 128;
    const int tx  = tid & 15;
    const int ty  = tid >> 4;
    const int arow = tid >> 1;
    const int acol = (tid & 1) * 4;
    const int brow = tid >> 5;
    const int bcol = (tid & 31) * 4;

    float acc[8][8];
#pragma unroll
    for (int i = 0; i < 8; i++)
#pragma unroll
        for (int j = 0; j < 8; j++) acc[i][j] = 0.f;

    for (int k0 = 0; k0 < K; k0 += 8) {
        float4 av = *reinterpret_cast<const float4*>(A + (long long)(bm + arow) * K + k0 + acol);
        float4 bv = *reinterpret_cast<const float4*>(B + (long long)(k0 + brow) * N + bn + bcol);
        __syncthreads();
        sA[acol + 0][arow] = av.x; sA[acol + 1][arow] = av.y;
        sA[acol + 2][arow] = av.z; sA[acol + 3][arow] = av.w;
        *reinterpret_cast<float4*>(&sB[brow][bcol]) = bv;
        __syncthreads();
#pragma unroll
        for (int kk = 0; kk < 8; kk++) {
            float a[8], bb[8];
#pragma unroll
            for (int i = 0; i < 8; i++) a[i]  = sA[kk][ty * 8 + i];
#pragma unroll
            for (int j = 0; j < 8; j++) bb[j] = sB[kk][tx * 8 + j];
#pragma unroll
            for (int i = 0; i < 8; i++)
#pragma unroll
                for (int j = 0; j < 8; j++)
                    acc[i][j] = fmaf(a[i], bb[j], acc[i][j]);
        }
    }

#pragma unroll
    for (int i = 0; i < 8; i++) {
        const int row = bm + ty * 8 + i;
#pragma unroll
        for (int j = 0; j < 8; j++) {
            const int col = bn + tx * 8 + j;
            float t = acc[i][j] + bias[row];
            if (MODE == 1) {
                Cout[(long long)col * M + row] = t;
            } else {
                Cout[(long long)row * N + col] = t;
                Cout[(long long)(row + 256) * N + col] = t * t;
            }
        }
    }
}

// ---------------------------------------------------------------------------
// Row softmax over 4096 columns, one block (256 thr) per row, in-place.
// ---------------------------------------------------------------------------
__global__ __launch_bounds__(256) void softmax_k()
{
    __shared__ float red[8];
    const size_t row = blockIdx.x;
    float4* p = reinterpret_cast<float4*>(g_S + row * (size_t)HW);
    const int tid = threadIdx.x;

    float4 v[4];
    float mx = -3.4e38f;
#pragma unroll
    for (int i = 0; i < 4; i++) {
        v[i] = p[tid + i * 256];
        mx = fmaxf(mx, fmaxf(fmaxf(v[i].x, v[i].y), fmaxf(v[i].z, v[i].w)));
    }
#pragma unroll
    for (int o = 16; o > 0; o >>= 1)
        mx = fmaxf(mx, __shfl_xor_sync(0xffffffffu, mx, o));
    if ((tid & 31) == 0) red[tid >> 5] = mx;
    __syncthreads();
    mx = red[0];
#pragma unroll
    for (int i = 1; i < 8; i++) mx = fmaxf(mx, red[i]);

    float s = 0.f;
#pragma unroll
    for (int i = 0; i < 4; i++) {
        v[i].x = __expf(v[i].x - mx); v[i].y = __expf(v[i].y - mx);
        v[i].z = __expf(v[i].z - mx); v[i].w = __expf(v[i].w - mx);
        s += v[i].x + v[i].y + v[i].z + v[i].w;
    }
#pragma unroll
    for (int o = 16; o > 0; o >>= 1)
        s += __shfl_xor_sync(0xffffffffu, s, o);
    __syncthreads();
    if ((tid & 31) == 0) red[tid >> 5] = s;
    __syncthreads();
    s = red[0];
#pragma unroll
    for (int i = 1; i < 8; i++) s += red[i];

    const float inv = 1.0f / s;
#pragma unroll
    for (int i = 0; i < 4; i++) {
        v[i].x *= inv; v[i].y *= inv; v[i].z *= inv; v[i].w *= inv;
        p[tid + i * 256] = v[i];
    }
}

// ---------------------------------------------------------------------------
__global__ __launch_bounds__(256) void stats_k(const float* __restrict__ content)
{
    __shared__ float r1[8];
    __shared__ float r2[8];
    const int bc = blockIdx.x;
    const float4* p = reinterpret_cast<const float4*>(content + (size_t)bc * HW);
    const int tid = threadIdx.x;

    float s = 0.f, s2 = 0.f;
#pragma unroll
    for (int i = 0; i < 4; i++) {
        float4 v = p[tid + i * 256];
        s  += v.x + v.y + v.z + v.w;
        s2 += v.x * v.x + v.y * v.y + v.z * v.z + v.w * v.w;
    }
#pragma unroll
    for (int o = 16; o > 0; o >>= 1) {
        s  += __shfl_xor_sync(0xffffffffu, s, o);
        s2 += __shfl_xor_sync(0xffffffffu, s2, o);
    }
    if ((tid & 31) == 0) { r1[tid >> 5] = s; r2[tid >> 5] = s2; }
    __syncthreads();
    if (tid == 0) {
        float ts = 0.f, ts2 = 0.f;
#pragma unroll
        for (int i = 0; i < 8; i++) { ts += r1[i]; ts2 += r2[i]; }
        float mean = ts * (1.0f / HW);
        float var  = (ts2 - (float)HW * mean * mean) * (1.0f / (HW - 1));
        g_cmean[bc] = mean;
        g_cinv[bc]  = rsqrtf(var + 1e-5f);
    }
}

// ---------------------------------------------------------------------------
__global__ __launch_bounds__(256) void final_k(const float* __restrict__ content,
                                               float* __restrict__ out)
{
    const size_t idx = (size_t)blockIdx.x * 256 + threadIdx.x;
    const int b = (int)(idx >> 20);
    const int c = (int)((idx >> 12) & 255);
    const int n = (int)(idx & 4095);
    const float* me = g_ME + ((size_t)(b * HW + n)) * (2 * CC);
    const float m  = me[c];
    const float e2 = me[CC + c];
    const float sd = sqrtf(fmaxf(e2 - m * m, 0.f));
    const int bc = b * CC + c;
    out[idx] = sd * (content[idx] - g_cmean[bc]) * g_cinv[bc] + m;
}

// ---------------------------------------------------------------------------
extern "C" void kernel_launch(void* const* d_in, const int* in_sizes, int n_in,
                              void* d_out, int out_size)
{
    const float* content = (const float*)d_in[0];
    const float* style   = (const float*)d_in[1];
    const float* ckey    = (const float*)d_in[2];
    const float* skey    = (const float*)d_in[3];
    const float* Wf = (const float*)d_in[4];
    const float* bf = (const float*)d_in[5];
    const float* Wg = (const float*)d_in[6];
    const float* bg = (const float*)d_in[7];
    const float* Wh = (const float*)d_in[8];
    const float* bh = (const float*)d_in[9];
    float* out = (float*)d_out;

    float *Q, *Kt, *VVt, *S, *ME;
    cudaGetSymbolAddress((void**)&Q,   g_Q);
    cudaGetSymbolAddress((void**)&Kt,  g_Kt);
    cudaGetSymbolAddress((void**)&VVt, g_VVt);
    cudaGetSymbolAddress((void**)&S,   g_S);
    cudaGetSymbolAddress((void**)&ME,  g_ME);

    const dim3 blk(256);
    const long long sCHW = (long long)CC * HW;

    // Projections (SIMT): outputs oriented for the tensor GEMMs
    sgemm_k<1><<<dim3(32, 2, BB), blk>>>(Wf, ckey, bf, Q,  CC, HW, CC, sCHW, sCHW);
    sgemm_k<1><<<dim3(32, 2, BB), blk>>>(Wg, skey, bg, Kt, CC, HW, CC, sCHW, sCHW);
    sgemm_k<4><<<dim3(32, 2, BB), blk>>>(Wh, style, bh, VVt, CC, HW, CC, sCHW, 2 * sCHW);

    // GEMM1 (HMMA, 3-pass fp16): S[n,m] = Q[n,:] . Kt[m,:]  (M=4096,N=4096,K=256)
    hmma_gemm<<<dim3(32, 32, BB), blk>>>(Q, Kt, S, CC, HW,
                                         sCHW, sCHW, (long long)HW * HW);

    // Row softmax (in place)
    softmax_k<<<BB * HW, blk>>>();

    // GEMM2 (HMMA, 3-pass fp16): ME[n,c2] = S[n,:] . VVt[c2,:] (M=4096,N=512,K=4096)
    hmma_gemm<<<dim3(4, 32, BB), blk>>>(S, VVt, ME, HW, 2 * CC,
                                        (long long)HW * HW, 2 * sCHW,
                                        (long long)HW * 2 * CC);

    // Content channel stats + final fused modulation
    stats_k<<<BB * CC, blk>>>(content);
    final_k<<<(BB * CC * HW) / 256, blk>>>(content, out);
}

// round 4
// speedup vs baseline: 2.3457x; 1.2649x over previous
#include <cuda_runtime.h>
#include <cuda_fp16.h>
#include <cstdint>

// Problem constants (fixed by the dataset)
#define BB 4
#define CC 256
#define HW 4096

// ---------------- scratch (no allocations allowed -> device globals) -------
__device__ __half g_Qh [(size_t)BB * HW * CC];
__device__ __half g_Ql [(size_t)BB * HW * CC];
__device__ __half g_Kth[(size_t)BB * HW * CC];
__device__ __half g_Ktl[(size_t)BB * HW * CC];
__device__ __half g_VVth[(size_t)BB * 2 * CC * HW];
__device__ __half g_VVtl[(size_t)BB * 2 * CC * HW];
__device__ __half g_Sh [(size_t)BB * HW * HW];
__device__ __half g_Sl [(size_t)BB * HW * HW];
__device__ float  g_S  [(size_t)BB * HW * HW];        // fp32 logits
__device__ float  g_ME [(size_t)BB * HW * 2 * CC];    // [b][n][mean|E2]
__device__ float  g_cmean[BB * CC];
__device__ float  g_cinv [BB * CC];

// =========================== PTX helpers (baseline, sm_80+) ================
#define LDSM4(r, addr) \
    asm volatile("ldmatrix.sync.aligned.m8n8.x4.shared.b16 {%0,%1,%2,%3}, [%4];" \
        : "=r"((r)[0]), "=r"((r)[1]), "=r"((r)[2]), "=r"((r)[3]) : "r"(addr))

#define MMA16816(d, a, b0, b1) \
    asm volatile("mma.sync.aligned.m16n8k16.row.col.f32.f16.f16.f32 " \
        "{%0,%1,%2,%3}, {%4,%5,%6,%7}, {%8,%9}, {%0,%1,%2,%3};" \
        : "+f"((d)[0]), "+f"((d)[1]), "+f"((d)[2]), "+f"((d)[3]) \
        : "r"((a)[0]), "r"((a)[1]), "r"((a)[2]), "r"((a)[3]), "r"(b0), "r"(b1))

#define CP16(dst, src) \
    asm volatile("cp.async.cg.shared.global [%0], [%1], 16;" :: "r"(dst), "l"(src))
#define CP_COMMIT() asm volatile("cp.async.commit_group;" ::: "memory")
#define CP_WAIT1()  asm volatile("cp.async.wait_group 1;" ::: "memory")
#define CP_WAIT0()  asm volatile("cp.async.wait_group 0;" ::: "memory")

__device__ __forceinline__ void split2(float a, float b, uint32_t& hi, uint32_t& lo) {
    __half h0 = __float2half_rn(a), h1 = __float2half_rn(b);
    __half l0 = __float2half_rn(a - __half2float(h0));
    __half l1 = __float2half_rn(b - __half2float(h1));
    __half2 H = __halves2half2(h0, h1), L = __halves2half2(l0, l1);
    hi = *reinterpret_cast<uint32_t*>(&H);
    lo = *reinterpret_cast<uint32_t*>(&L);
}

// ===========================================================================
// HMMA 3-pass split GEMM on pre-split fp16:  C = A @ B^T  (fp32 out)
// A = Ah+Al [M][K], B = Bh+Bl [N][K]. CTA 128x128, 8 warps (4Mx2N),
// warp tile 32x64. k-step 64, double-buffered cp.async stages (128KB smem).
// grid = (N/128, M/128, batch)
// ===========================================================================
#define STAGE_BYTES 65536
#define OFF_AH 0
#define OFF_AL 16384
#define OFF_BH 32768
#define OFF_BL 49152

__global__ __launch_bounds__(256) void hmma2(
    const __half* __restrict__ Ah, const __half* __restrict__ Al,
    const __half* __restrict__ Bh, const __half* __restrict__ Bl,
    float* __restrict__ C, int K, int ldc,
    long long strA, long long strB, long long strC)
{
    extern __shared__ char smem[];
    const uint32_t uS = (uint32_t)__cvta_generic_to_shared(smem);

    const int tid  = threadIdx.x;
    const int lane = tid & 31;
    const int wid  = tid >> 5;
    const int wm   = wid & 3;
    const int wn   = wid >> 2;

    const long long aoff = blockIdx.z * strA + (long long)(blockIdx.y * 128) * K;
    const long long boff = blockIdx.z * strB + (long long)(blockIdx.x * 128) * K;
    Ah += aoff; Al += aoff; Bh += boff; Bl += boff;
    C += blockIdx.z * strC + (long long)(blockIdx.y * 128) * ldc + blockIdx.x * 128;

    // cp.async mapping: col fixed per thread, 4 rows per tile
    const int lr  = tid >> 3;        // 0..31
    const int col = tid & 7;         // 16B chunk within 128B row
    const uint32_t dst0 = lr * 128 + ((col * 16) ^ ((lr & 7) << 4));
    const __half* tAh = Ah + (size_t)lr * K + col * 8;
    const __half* tAl = Al + (size_t)lr * K + col * 8;
    const __half* tBh = Bh + (size_t)lr * K + col * 8;
    const __half* tBl = Bl + (size_t)lr * K + col * 8;

    auto load_stage = [&](int stage, int k0) {
        const uint32_t sb = uS + stage * STAGE_BYTES + dst0;
#pragma unroll
        for (int i = 0; i < 4; i++) {
            const size_t go = (size_t)i * 32 * K + k0;
            CP16(sb + OFF_AH + i * 4096, tAh + go);
            CP16(sb + OFF_AL + i * 4096, tAl + go);
            CP16(sb + OFF_BH + i * 4096, tBh + go);
            CP16(sb + OFF_BL + i * 4096, tBl + go);
        }
        CP_COMMIT();
    };

    float acc[2][8][4];
#pragma unroll
    for (int i = 0; i < 2; i++)
#pragma unroll
        for (int j = 0; j < 8; j++)
#pragma unroll
            for (int t = 0; t < 4; t++) acc[i][j][t] = 0.f;

    const int NK = K >> 6;
    load_stage(0, 0);
    load_stage(1, 64);

    const int grp  = lane >> 3;
    const int lrow = lane & 7;
    const int arow = wm * 32 + lrow + ((grp & 1) << 3);

    for (int ks = 0; ks < NK; ks++) {
        if (ks + 1 < NK) CP_WAIT1(); else CP_WAIT0();
        __syncthreads();

        const uint32_t sb  = uS + (ks & 1) * STAGE_BYTES;
#pragma unroll
        for (int ksub = 0; ksub < 4; ksub++) {
            const int colb = (ksub * 2 + (grp >> 1)) * 16;
            uint32_t aH[2][4], aL[2][4];
#pragma unroll
            for (int mt = 0; mt < 2; mt++) {
                const int row = arow + mt * 16;
                const uint32_t off = row * 128 + (colb ^ ((row & 7) << 4));
                LDSM4(aH[mt], sb + OFF_AH + off);
                LDSM4(aL[mt], sb + OFF_AL + off);
            }
#pragma unroll
            for (int nt4 = 0; nt4 < 4; nt4++) {
                const int brow = wn * 64 + nt4 * 16 + lrow + ((grp & 1) << 3);
                const uint32_t boff2 = brow * 128 + (colb ^ ((brow & 7) << 4));
                uint32_t bh[4], bl[4];
                LDSM4(bh, sb + OFF_BH + boff2);
                LDSM4(bl, sb + OFF_BL + boff2);
#pragma unroll
                for (int mt = 0; mt < 2; mt++) {
                    MMA16816(acc[mt][nt4 * 2],     aH[mt], bh[0], bh[2]);
                    MMA16816(acc[mt][nt4 * 2],     aL[mt], bh[0], bh[2]);
                    MMA16816(acc[mt][nt4 * 2],     aH[mt], bl[0], bl[2]);
                    MMA16816(acc[mt][nt4 * 2 + 1], aH[mt], bh[1], bh[3]);
                    MMA16816(acc[mt][nt4 * 2 + 1], aL[mt], bh[1], bh[3]);
                    MMA16816(acc[mt][nt4 * 2 + 1], aH[mt], bl[1], bl[3]);
                }
            }
        }
        __syncthreads();
        if (ks + 2 < NK) load_stage(ks & 1, (ks + 2) * 64);
    }

    // ---- epilogue: fragment store ----
#pragma unroll
    for (int mt = 0; mt < 2; mt++) {
        const int lr2 = wm * 32 + mt * 16 + (lane >> 2);
#pragma unroll
        for (int nt = 0; nt < 8; nt++) {
            const int c2 = wn * 64 + nt * 8 + (lane & 3) * 2;
            *reinterpret_cast<float2*>(C + (long long)lr2 * ldc + c2) =
                make_float2(acc[mt][nt][0], acc[mt][nt][1]);
            *reinterpret_cast<float2*>(C + (long long)(lr2 + 8) * ldc + c2) =
                make_float2(acc[mt][nt][2], acc[mt][nt][3]);
        }
    }
}

// ===========================================================================
// SIMT projections: R[o,p] = W[o,c] X[b,c,p] + bias[o]   (M=256,N=4096,K=256)
// MODE 1: split(v+bias) -> H/L at [col*M+row]  (pixel-major: Q, Kt)
// MODE 4: t and t*t split -> H/L at [row*N+col], [(row+256)*N+col]  (VVt)
// ===========================================================================
template <int MODE>
__global__ __launch_bounds__(256) void sgemm_k(
    const float* __restrict__ A, const float* __restrict__ B,
    const float* __restrict__ bias,
    __half* __restrict__ OH, __half* __restrict__ OL,
    int M, int N, int K, long long strB, long long strC)
{
    B  += (long long)blockIdx.z * strB;
    OH += (long long)blockIdx.z * strC;
    OL += (long long)blockIdx.z * strC;

    __shared__ float sA[8][128];
    __shared__ float sB[8][128];

    const int tid = threadIdx.x;
    const int bm  = blockIdx.y * 128;
    const int bn  = blockIdx.x * 128;
    const int tx  = tid & 15;
    const int ty  = tid >> 4;
    const int ar  = tid >> 1;
    const int ac  = (tid & 1) * 4;
    const int br  = tid >> 5;
    const int bc  = (tid & 31) * 4;

    float acc[8][8];
#pragma unroll
    for (int i = 0; i < 8; i++)
#pragma unroll
        for (int j = 0; j < 8; j++) acc[i][j] = 0.f;

    for (int k0 = 0; k0 < K; k0 += 8) {
        float4 av = *reinterpret_cast<const float4*>(A + (long long)(bm + ar) * K + k0 + ac);
        float4 bv = *reinterpret_cast<const float4*>(B + (long long)(k0 + br) * N + bn + bc);
        __syncthreads();
        sA[ac + 0][ar] = av.x; sA[ac + 1][ar] = av.y;
        sA[ac + 2][ar] = av.z; sA[ac + 3][ar] = av.w;
        *reinterpret_cast<float4*>(&sB[br][bc]) = bv;
        __syncthreads();
#pragma unroll
        for (int kk = 0; kk < 8; kk++) {
            float a[8], bb[8];
#pragma unroll
            for (int i = 0; i < 8; i++) a[i]  = sA[kk][ty * 8 + i];
#pragma unroll
            for (int j = 0; j < 8; j++) bb[j] = sB[kk][tx * 8 + j];
#pragma unroll
            for (int i = 0; i < 8; i++)
#pragma unroll
                for (int j = 0; j < 8; j++)
                    acc[i][j] = fmaf(a[i], bb[j], acc[i][j]);
        }
    }

#pragma unroll
    for (int i = 0; i < 8; i++) {
        const int row = bm + ty * 8 + i;
        const float bs = bias[row];
#pragma unroll
        for (int j = 0; j < 8; j++) {
            const int colj = bn + tx * 8 + j;
            float t = acc[i][j] + bs;
            if (MODE == 1) {
                __half h = __float2half_rn(t);
                __half l = __float2half_rn(t - __half2float(h));
                OH[(long long)colj * M + row] = h;
                OL[(long long)colj * M + row] = l;
            } else {
                __half h = __float2half_rn(t);
                __half l = __float2half_rn(t - __half2float(h));
                OH[(long long)row * N + colj] = h;
                OL[(long long)row * N + colj] = l;
                float t2 = t * t;
                __half h2 = __float2half_rn(t2);
                __half l2 = __float2half_rn(t2 - __half2float(h2));
                OH[(long long)(row + 256) * N + colj] = h2;
                OL[(long long)(row + 256) * N + colj] = l2;
            }
        }
    }
}

// ---------------------------------------------------------------------------
// Row softmax over 4096 cols; reads fp32 logits, writes hi/lo fp16 weights.
// ---------------------------------------------------------------------------
__global__ __launch_bounds__(256) void softmax_k()
{
    __shared__ float red[8];
    const size_t row = blockIdx.x;
    const float4* p = reinterpret_cast<const float4*>(g_S + row * (size_t)HW);
    uint2* ph = reinterpret_cast<uint2*>(g_Sh + row * (size_t)HW);
    uint2* pl = reinterpret_cast<uint2*>(g_Sl + row * (size_t)HW);
    const int tid = threadIdx.x;

    float4 v[4];
    float mx = -3.4e38f;
#pragma unroll
    for (int i = 0; i < 4; i++) {
        v[i] = p[tid + i * 256];
        mx = fmaxf(mx, fmaxf(fmaxf(v[i].x, v[i].y), fmaxf(v[i].z, v[i].w)));
    }
#pragma unroll
    for (int o = 16; o > 0; o >>= 1)
        mx = fmaxf(mx, __shfl_xor_sync(0xffffffffu, mx, o));
    if ((tid & 31) == 0) red[tid >> 5] = mx;
    __syncthreads();
    mx = red[0];
#pragma unroll
    for (int i = 1; i < 8; i++) mx = fmaxf(mx, red[i]);

    float s = 0.f;
#pragma unroll
    for (int i = 0; i < 4; i++) {
        v[i].x = __expf(v[i].x - mx); v[i].y = __expf(v[i].y - mx);
        v[i].z = __expf(v[i].z - mx); v[i].w = __expf(v[i].w - mx);
        s += v[i].x + v[i].y + v[i].z + v[i].w;
    }
#pragma unroll
    for (int o = 16; o > 0; o >>= 1)
        s += __shfl_xor_sync(0xffffffffu, s, o);
    __syncthreads();
    if ((tid & 31) == 0) red[tid >> 5] = s;
    __syncthreads();
    s = red[0];
#pragma unroll
    for (int i = 1; i < 8; i++) s += red[i];

    const float inv = 1.0f / s;
#pragma unroll
    for (int i = 0; i < 4; i++) {
        float w0 = v[i].x * inv, w1 = v[i].y * inv;
        float w2 = v[i].z * inv, w3 = v[i].w * inv;
        uint32_t h01, l01, h23, l23;
        split2(w0, w1, h01, l01);
        split2(w2, w3, h23, l23);
        ph[tid + i * 256] = make_uint2(h01, h23);
        pl[tid + i * 256] = make_uint2(l01, l23);
    }
}

// ---------------------------------------------------------------------------
__global__ __launch_bounds__(256) void stats_k(const float* __restrict__ content)
{
    __shared__ float r1[8];
    __shared__ float r2[8];
    const int bc = blockIdx.x;
    const float4* p = reinterpret_cast<const float4*>(content + (size_t)bc * HW);
    const int tid = threadIdx.x;

    float s = 0.f, s2 = 0.f;
#pragma unroll
    for (int i = 0; i < 4; i++) {
        float4 v = p[tid + i * 256];
        s  += v.x + v.y + v.z + v.w;
        s2 += v.x * v.x + v.y * v.y + v.z * v.z + v.w * v.w;
    }
#pragma unroll
    for (int o = 16; o > 0; o >>= 1) {
        s  += __shfl_xor_sync(0xffffffffu, s, o);
        s2 += __shfl_xor_sync(0xffffffffu, s2, o);
    }
    if ((tid & 31) == 0) { r1[tid >> 5] = s; r2[tid >> 5] = s2; }
    __syncthreads();
    if (tid == 0) {
        float ts = 0.f, ts2 = 0.f;
#pragma unroll
        for (int i = 0; i < 8; i++) { ts += r1[i]; ts2 += r2[i]; }
        float mean = ts * (1.0f / HW);
        float var  = (ts2 - (float)HW * mean * mean) * (1.0f / (HW - 1));
        g_cmean[bc] = mean;
        g_cinv[bc]  = rsqrtf(var + 1e-5f);
    }
}

// ---------------------------------------------------------------------------
__global__ __launch_bounds__(256) void final_k(const float* __restrict__ content,
                                               float* __restrict__ out)
{
    const size_t idx = (size_t)blockIdx.x * 256 + threadIdx.x;
    const int b = (int)(idx >> 20);
    const int c = (int)((idx >> 12) & 255);
    const int n = (int)(idx & 4095);
    const float* me = g_ME + ((size_t)(b * HW + n)) * (2 * CC);
    const float m  = me[c];
    const float e2 = me[CC + c];
    const float sd = sqrtf(fmaxf(e2 - m * m, 0.f));
    const int bc = b * CC + c;
    out[idx] = sd * (content[idx] - g_cmean[bc]) * g_cinv[bc] + m;
}

// ---------------------------------------------------------------------------
extern "C" void kernel_launch(void* const* d_in, const int* in_sizes, int n_in,
                              void* d_out, int out_size)
{
    const float* content = (const float*)d_in[0];
    const float* style   = (const float*)d_in[1];
    const float* ckey    = (const float*)d_in[2];
    const float* skey    = (const float*)d_in[3];
    const float* Wf = (const float*)d_in[4];
    const float* bf = (const float*)d_in[5];
    const float* Wg = (const float*)d_in[6];
    const float* bg = (const float*)d_in[7];
    const float* Wh = (const float*)d_in[8];
    const float* bh = (const float*)d_in[9];
    float* out = (float*)d_out;

    __half *Qh, *Ql, *Kth, *Ktl, *VVth, *VVtl, *Sh, *Sl;
    float *S, *ME;
    cudaGetSymbolAddress((void**)&Qh,  g_Qh);
    cudaGetSymbolAddress((void**)&Ql,  g_Ql);
    cudaGetSymbolAddress((void**)&Kth, g_Kth);
    cudaGetSymbolAddress((void**)&Ktl, g_Ktl);
    cudaGetSymbolAddress((void**)&VVth, g_VVth);
    cudaGetSymbolAddress((void**)&VVtl, g_VVtl);
    cudaGetSymbolAddress((void**)&Sh,  g_Sh);
    cudaGetSymbolAddress((void**)&Sl,  g_Sl);
    cudaGetSymbolAddress((void**)&S,   g_S);
    cudaGetSymbolAddress((void**)&ME,  g_ME);

    static bool attr_set = false;
    if (!attr_set) {
        cudaFuncSetAttribute(hmma2, cudaFuncAttributeMaxDynamicSharedMemorySize,
                             2 * STAGE_BYTES);
        attr_set = true;
    }

    const dim3 blk(256);
    const long long sCHW = (long long)CC * HW;

    // Projections (SIMT, fp32 in -> pre-split fp16 out)
    sgemm_k<1><<<dim3(32, 2, BB), blk>>>(Wf, ckey, bf, Qh, Ql, CC, HW, CC, sCHW, sCHW);
    sgemm_k<1><<<dim3(32, 2, BB), blk>>>(Wg, skey, bg, Kth, Ktl, CC, HW, CC, sCHW, sCHW);
    sgemm_k<4><<<dim3(32, 2, BB), blk>>>(Wh, style, bh, VVth, VVtl, CC, HW, CC,
                                         sCHW, 2 * sCHW);

    // GEMM1: S[n,m] = Q[n,:] . Kt[m,:]   (M=4096,N=4096,K=256)
    hmma2<<<dim3(32, 32, BB), blk, 2 * STAGE_BYTES>>>(
        Qh, Ql, Kth, Ktl, S, CC, HW, sCHW, sCHW, (long long)HW * HW);

    // Row softmax -> split fp16 weights
    softmax_k<<<BB * HW, blk>>>();

    // GEMM2: ME[n,c2] = S[n,:] . VVt[c2,:]   (M=4096,N=512,K=4096)
    hmma2<<<dim3(4, 32, BB), blk, 2 * STAGE_BYTES>>>(
        Sh, Sl, VVth, VVtl, ME, HW, 2 * CC,
        (long long)HW * HW, 2 * sCHW, (long long)HW * 2 * CC);

    // Content channel stats + final fused modulation
    stats_k<<<BB * CC, blk>>>(content);
    final_k<<<(BB * CC * HW) / 256, blk>>>(content, out);
}